// round 3
// baseline (speedup 1.0000x reference)
#include <cuda_runtime.h>
#include <math.h>

#define TT 256
#define BB 64
#define DD 1024
#define HH 2048
#define KB 16            // split-K blocks in the recurrent GEMM
#define KS (HH / KB)     // 128
#define NBLK 16          // HH / 128 n-blocks

typedef unsigned long long ull;

// Scratch (no cudaMalloc allowed)
__device__ __align__(16) float g_xproj[(size_t)TT * BB * HH];   // 128 MB
__device__ __align__(16) float g_part[(size_t)KB * BB * HH];    // 8 MB
__device__ int g_cnt[NBLK];                                     // zero-init

// ---- packed f32x2 helpers -------------------------------------------------
__device__ __forceinline__ ull pack2(float x, float y) {
    ull r; asm("mov.b64 %0, {%1, %2};" : "=l"(r) : "f"(x), "f"(y)); return r;
}
__device__ __forceinline__ void unpack2(ull v, float& x, float& y) {
    asm("mov.b64 {%0, %1}, %2;" : "=f"(x), "=f"(y) : "l"(v));
}
__device__ __forceinline__ void fma2(ull& d, ull a, ull b) {
    asm("fma.rn.f32x2 %0, %1, %2, %0;" : "+l"(d) : "l"(a), "l"(b));
}

// ---------------------------------------------------------------------------
// x_proj = inputs[16384,1024] @ W_xh[1024,2048] + b_h
// CTA tile [128m x 128n], 256 threads, 8x8 microtile, f32x2 inner, chunk K=16.
// ---------------------------------------------------------------------------
__global__ void __launch_bounds__(256) xproj_kernel(
    const float* __restrict__ A,      // [M, DD]
    const float* __restrict__ B,      // [DD, HH]
    const float* __restrict__ bias)
{
    const int nb = blockIdx.x;        // 0..15
    const int mb = blockIdx.y;        // 0..127
    const int tid = threadIdx.x;
    const int tx = tid & 15;
    const int ty = tid >> 4;          // 0..15
    const int nbase = nb * 128;
    const int mbase = mb * 128;

    __shared__ __align__(16) float As[16][128];   // As[k][m]
    __shared__ __align__(16) float Bs[16][128];   // Bs[k][n]

    ull acc[8][4];
#pragma unroll
    for (int i = 0; i < 8; i++)
#pragma unroll
        for (int j = 0; j < 4; j++) acc[i][j] = 0ULL;

    float4 areg[2], breg[2];
    // prefetch chunk 0
#pragma unroll
    for (int it = 0; it < 2; it++) {
        int idx = tid + it * 256;           // 0..511
        int m = idx >> 2, kq = idx & 3;
        areg[it] = *(const float4*)(A + (size_t)(mbase + m) * DD + kq * 4);
        int kk = idx >> 5, c4 = idx & 31;
        breg[it] = *(const float4*)(B + (size_t)kk * HH + nbase + c4 * 4);
    }

    for (int ch = 0; ch < DD / 16; ch++) {
#pragma unroll
        for (int it = 0; it < 2; it++) {
            int idx = tid + it * 256;
            int m = idx >> 2, kq = idx & 3;
            As[kq * 4 + 0][m] = areg[it].x;
            As[kq * 4 + 1][m] = areg[it].y;
            As[kq * 4 + 2][m] = areg[it].z;
            As[kq * 4 + 3][m] = areg[it].w;
            int kk = idx >> 5, c4 = idx & 31;
            *(float4*)&Bs[kk][c4 * 4] = breg[it];
        }
        __syncthreads();
        if (ch + 1 < DD / 16) {
            const int k0 = (ch + 1) * 16;
#pragma unroll
            for (int it = 0; it < 2; it++) {
                int idx = tid + it * 256;
                int m = idx >> 2, kq = idx & 3;
                areg[it] = *(const float4*)(A + (size_t)(mbase + m) * DD + k0 + kq * 4);
                int kk = idx >> 5, c4 = idx & 31;
                breg[it] = *(const float4*)(B + (size_t)(k0 + kk) * HH + nbase + c4 * 4);
            }
        }
#pragma unroll
        for (int k = 0; k < 16; k++) {
            float4 a0 = *(const float4*)&As[k][ty * 4];
            float4 a1 = *(const float4*)&As[k][64 + ty * 4];
            ulonglong2 b0 = *(const ulonglong2*)&Bs[k][tx * 4];
            ulonglong2 b1 = *(const ulonglong2*)&Bs[k][64 + tx * 4];
            float a[8] = {a0.x, a0.y, a0.z, a0.w, a1.x, a1.y, a1.z, a1.w};
#pragma unroll
            for (int i = 0; i < 8; i++) {
                ull a2 = pack2(a[i], a[i]);
                fma2(acc[i][0], a2, b0.x);
                fma2(acc[i][1], a2, b0.y);
                fma2(acc[i][2], a2, b1.x);
                fma2(acc[i][3], a2, b1.y);
            }
        }
        __syncthreads();
    }

#pragma unroll
    for (int i = 0; i < 8; i++) {
        int r = (i < 4) ? (ty * 4 + i) : (64 + ty * 4 + i - 4);
        float o[8];
        unpack2(acc[i][0], o[0], o[1]);
        unpack2(acc[i][1], o[2], o[3]);
        unpack2(acc[i][2], o[4], o[5]);
        unpack2(acc[i][3], o[6], o[7]);
#pragma unroll
        for (int h = 0; h < 2; h++) {
            int col = nbase + h * 64 + tx * 4;
            float4 v;
            v.x = o[h * 4 + 0] + bias[col + 0];
            v.y = o[h * 4 + 1] + bias[col + 1];
            v.z = o[h * 4 + 2] + bias[col + 2];
            v.w = o[h * 4 + 3] + bias[col + 3];
            *(float4*)&g_xproj[(size_t)(mbase + r) * HH + col] = v;
        }
    }
}

// ---------------------------------------------------------------------------
// One recurrence step: h_out = tanh(h_prev[64,2048] @ W[2048,2048] + xproj[t])
// grid (16 nb, 16 kb), 128 threads. CTA [64m x 128n] over a 128-wide K slice.
// 8x8 microtile, f32x2 inner. Last-arriving CTA per nb reduces + tanh.
// ---------------------------------------------------------------------------
__global__ void __launch_bounds__(128) step_kernel(
    const float* __restrict__ h_prev,
    const float* __restrict__ W,
    int t,
    float* __restrict__ h_out)
{
    const int nb = blockIdx.x;        // 0..15
    const int kb = blockIdx.y;        // 0..15
    const int tid = threadIdx.x;
    const int tx = tid & 15;
    const int ty = tid >> 4;          // 0..7
    const int nbase = nb * 128;
    const int k0base = kb * KS;

    __shared__ __align__(16) float hs[16][64];    // hs[k][m]
    __shared__ __align__(16) float ws[16][128];   // ws[k][n]
    __shared__ int s_last;

    ull acc[8][4];
#pragma unroll
    for (int i = 0; i < 8; i++)
#pragma unroll
        for (int j = 0; j < 4; j++) acc[i][j] = 0ULL;

    float4 hreg[2], wreg[4];
    // prefetch chunk 0
#pragma unroll
    for (int it = 0; it < 2; it++) {
        int idx = tid + it * 128;     // 0..255
        int m = idx >> 2, kq = idx & 3;
        hreg[it] = *(const float4*)(h_prev + (size_t)m * HH + k0base + kq * 4);
    }
#pragma unroll
    for (int it = 0; it < 4; it++) {
        int idx = tid + it * 128;     // 0..511
        int kk = idx >> 5, c4 = idx & 31;
        wreg[it] = *(const float4*)(W + (size_t)(k0base + kk) * HH + nbase + c4 * 4);
    }

    for (int ch = 0; ch < KS / 16; ch++) {   // 8 chunks
#pragma unroll
        for (int it = 0; it < 2; it++) {
            int idx = tid + it * 128;
            int m = idx >> 2, kq = idx & 3;
            hs[kq * 4 + 0][m] = hreg[it].x;
            hs[kq * 4 + 1][m] = hreg[it].y;
            hs[kq * 4 + 2][m] = hreg[it].z;
            hs[kq * 4 + 3][m] = hreg[it].w;
        }
#pragma unroll
        for (int it = 0; it < 4; it++) {
            int idx = tid + it * 128;
            int kk = idx >> 5, c4 = idx & 31;
            *(float4*)&ws[kk][c4 * 4] = wreg[it];
        }
        __syncthreads();
        if (ch + 1 < KS / 16) {
            const int k0 = k0base + (ch + 1) * 16;
#pragma unroll
            for (int it = 0; it < 2; it++) {
                int idx = tid + it * 128;
                int m = idx >> 2, kq = idx & 3;
                hreg[it] = *(const float4*)(h_prev + (size_t)m * HH + k0 + kq * 4);
            }
#pragma unroll
            for (int it = 0; it < 4; it++) {
                int idx = tid + it * 128;
                int kk = idx >> 5, c4 = idx & 31;
                wreg[it] = *(const float4*)(W + (size_t)(k0 + kk) * HH + nbase + c4 * 4);
            }
        }
#pragma unroll
        for (int k = 0; k < 16; k++) {
            float4 a0 = *(const float4*)&hs[k][ty * 4];
            float4 a1 = *(const float4*)&hs[k][32 + ty * 4];
            ulonglong2 b0 = *(const ulonglong2*)&ws[k][tx * 4];
            ulonglong2 b1 = *(const ulonglong2*)&ws[k][64 + tx * 4];
            float a[8] = {a0.x, a0.y, a0.z, a0.w, a1.x, a1.y, a1.z, a1.w};
#pragma unroll
            for (int i = 0; i < 8; i++) {
                ull a2 = pack2(a[i], a[i]);
                fma2(acc[i][0], a2, b0.x);
                fma2(acc[i][1], a2, b0.y);
                fma2(acc[i][2], a2, b1.x);
                fma2(acc[i][3], a2, b1.y);
            }
        }
        __syncthreads();
    }

    // unpack own tile, write partial
    float o[8][8];
#pragma unroll
    for (int i = 0; i < 8; i++) {
        unpack2(acc[i][0], o[i][0], o[i][1]);
        unpack2(acc[i][1], o[i][2], o[i][3]);
        unpack2(acc[i][2], o[i][4], o[i][5]);
        unpack2(acc[i][3], o[i][6], o[i][7]);
    }
    float* P = g_part + (size_t)kb * BB * HH;
#pragma unroll
    for (int i = 0; i < 8; i++) {
        int r = (i < 4) ? (ty * 4 + i) : (32 + ty * 4 + i - 4);
#pragma unroll
        for (int h = 0; h < 2; h++) {
            float4 v;
            v.x = o[i][h * 4 + 0]; v.y = o[i][h * 4 + 1];
            v.z = o[i][h * 4 + 2]; v.w = o[i][h * 4 + 3];
            *(float4*)&P[(size_t)r * HH + nbase + h * 64 + tx * 4] = v;
        }
    }
    __threadfence();
    __syncthreads();
    if (tid == 0) {
        int c = atomicAdd(&g_cnt[nb], 1);
        s_last = (c == KB - 1) ? 1 : 0;
        if (c == KB - 1) g_cnt[nb] = 0;    // reset for next step's launch
    }
    __syncthreads();
    if (!s_last) return;

    // Epilogue: fuse own register tile + 15 gmem partials, + x_proj, tanh.
    const float* xp = g_xproj + (size_t)t * BB * HH;
#pragma unroll
    for (int i = 0; i < 8; i++) {
        int r = (i < 4) ? (ty * 4 + i) : (32 + ty * 4 + i - 4);
#pragma unroll
        for (int h = 0; h < 2; h++) {
            size_t off = (size_t)r * HH + nbase + h * 64 + tx * 4;
            float4 s;
            s.x = o[i][h * 4 + 0]; s.y = o[i][h * 4 + 1];
            s.z = o[i][h * 4 + 2]; s.w = o[i][h * 4 + 3];
#pragma unroll
            for (int k2 = 0; k2 < KB; k2++) {
                if (k2 == kb) continue;
                float4 p = *(const float4*)&g_part[(size_t)k2 * BB * HH + off];
                s.x += p.x; s.y += p.y; s.z += p.z; s.w += p.w;
            }
            float4 xv = *(const float4*)&xp[off];
            float4 rr;
            rr.x = tanhf(s.x + xv.x);
            rr.y = tanhf(s.y + xv.y);
            rr.z = tanhf(s.z + xv.z);
            rr.w = tanhf(s.w + xv.w);
            *(float4*)&h_out[off] = rr;
        }
    }
}

// final_state = outputs[T-1]
__global__ void __launch_bounds__(256) copy_final(const float* __restrict__ src,
                                                  float* __restrict__ dst)
{
    const int i = blockIdx.x * 256 + threadIdx.x;
    ((float4*)dst)[i] = ((const float4*)src)[i];
}

extern "C" void kernel_launch(void* const* d_in, const int* in_sizes, int n_in,
                              void* d_out, int out_size)
{
    (void)in_sizes; (void)n_in; (void)out_size;
    const float* inputs = (const float*)d_in[0];   // [T,B,D]
    const float* state  = (const float*)d_in[1];   // [B,H]
    const float* W_xh   = (const float*)d_in[2];   // [D,H]
    const float* W_hh   = (const float*)d_in[3];   // [H,H]
    const float* b_h    = (const float*)d_in[4];   // [H]
    float* out = (float*)d_out;   // outputs [T,B,H] then final_state [B,H]

    // 1) x_proj for all steps
    xproj_kernel<<<dim3(NBLK, (TT * BB) / 128), 256>>>(inputs, W_xh, b_h);

    // 2) sequential scan
    const float* h_prev = state;
    for (int t = 0; t < TT; t++) {
        float* h_out = out + (size_t)t * BB * HH;
        step_kernel<<<dim3(NBLK, KB), 128>>>(h_prev, W_hh, t, h_out);
        h_prev = h_out;
    }

    // 3) final_state = outputs[T-1]
    copy_final<<<(BB * HH / 4) / 256, 256>>>(out + (size_t)(TT - 1) * BB * HH,
                                             out + (size_t)TT * BB * HH);
}

// round 5
// speedup vs baseline: 1.6037x; 1.6037x over previous
#include <cuda_runtime.h>
#include <math.h>

#define TT 256
#define BB 64
#define DD 1024
#define HH 2048

#define GRID 128
#define THREADS 256
#define NBD 8            // n-blocks (each 256 wide)
#define KBD 16           // k-blocks (each 128 deep)
#define NSL 256
#define KSL 128
#define STEP_ELEMS (BB * HH)   // 131072

typedef unsigned long long ull;

// Scratch (no cudaMalloc allowed)
__device__ __align__(16) float g_xproj[(size_t)TT * BB * HH];   // 128 MB
__device__ __align__(16) float g_part[(size_t)KBD * BB * HH];   // 8 MB
__device__ unsigned g_arrive;    // zero-init; self-resetting
__device__ unsigned g_release;   // monotonic epoch counter

// ---- packed f32x2 helpers ---------------------------------------------------
__device__ __forceinline__ ull pack2(float x, float y) {
    ull r; asm("mov.b64 %0, {%1, %2};" : "=l"(r) : "f"(x), "f"(y)); return r;
}
__device__ __forceinline__ void unpack2(ull v, float& x, float& y) {
    asm("mov.b64 {%0, %1}, %2;" : "=f"(x), "=f"(y) : "l"(v));
}
__device__ __forceinline__ void fma2(ull& d, ull a, ull b) {
    asm("fma.rn.f32x2 %0, %1, %2, %0;" : "+l"(d) : "l"(a), "l"(b));
}

// ---- grid barrier with proper release/acquire ordering ----------------------
// Writer side: __threadfence() (release) before arriving. Leader publishes via
// atomicAdd after fencing the counter reset. Spinners use ld.acquire.gpu and
// an explicit __threadfence() before bar.sync so the ordering extends to every
// thread of the CTA (standard cooperative grid.sync pattern).
__device__ __forceinline__ void grid_barrier(unsigned& epoch) {
    __syncthreads();
    if (threadIdx.x == 0) {
        __threadfence();   // release: all prior writes visible before arrive
        unsigned a = atomicAdd(&g_arrive, 1u);
        if (a == GRID - 1) {
            atomicExch(&g_arrive, 0u);
            __threadfence();
            atomicAdd(&g_release, 1u);
        } else {
            unsigned r;
            do {
                asm volatile("ld.acquire.gpu.u32 %0, [%1];"
                             : "=r"(r) : "l"(&g_release));
            } while (r == epoch);
        }
        __threadfence();   // acquire side: order subsequent reads (leader + spinners)
    }
    epoch += 1;
    __syncthreads();       // CTA-wide propagation of the happens-before edge
}

// -----------------------------------------------------------------------------
// Persistent scan kernel: all 256 recurrence steps in one launch.
// CTA (nb, kb) keeps W_hh[kb*128 : +128, nb*256 : +256] resident in SMEM.
// Per step: partial [64x256] GEMM over its K-slice -> g_part[kb]; grid barrier;
// distributed 16-way reduce + x_proj + tanh -> out[t]; grid barrier.
// -----------------------------------------------------------------------------
extern __shared__ float smem[];   // ws[128][256] (128 KB) + hs[2][64][68] (34 KB)

__global__ void __launch_bounds__(THREADS) scan_kernel(
    const float* __restrict__ state,
    const float* __restrict__ W,
    float* __restrict__ out)
{
    float* ws = smem;                       // [KSL][NSL]
    float* hsb = smem + KSL * NSL;          // [2][64][68]
    const int HPAD = 68;
    const int HBUF = 64 * HPAD;

    const int tid = threadIdx.x;
    const int cta = blockIdx.x;
    const int nb = cta & (NBD - 1);
    const int kb = cta >> 3;                // 0..15
    const int nbase = nb * NSL;
    const int k0 = kb * KSL;
    const int tx = tid & 15;                // n: 4 groups of 4 at q*64 + tx*4
    const int ty = tid >> 4;                // m: 4 rows at ty*4

    // ---- load resident W slice (once) ----
#pragma unroll
    for (int i = 0; i < 32; i++) {
        int idx = i * THREADS + tid;        // 0..8191 float4s
        int k = idx >> 6;
        int c4 = (idx & 63) * 4;
        *(float4*)&ws[k * NSL + c4] =
            *(const float4*)&W[(size_t)(k0 + k) * HH + nbase + c4];
    }
    __syncthreads();

    unsigned epoch;
    {
        unsigned r;
        asm volatile("ld.acquire.gpu.u32 %0, [%1];" : "=r"(r) : "l"(&g_release));
        epoch = r;   // stable: release can't advance until all CTAs arrive once
    }

    // epilogue mapping (fixed per thread)
    const int g = cta * THREADS + tid;      // 0..32767 float4 slots
    const int em = g >> 9;
    const int ec4 = (g & 511) * 4;
    const size_t eoff = (size_t)em * HH + ec4;

    for (int t = 0; t < TT; t++) {
        const float* hp = (t == 0) ? state : (out + (size_t)(t - 1) * STEP_ELEMS);

        ull acc[4][8];
#pragma unroll
        for (int i = 0; i < 4; i++)
#pragma unroll
            for (int j = 0; j < 8; j++) acc[i][j] = 0ULL;

        // prefetch chunk 0 of h (64 k x 64 m)
        float4 hreg[4];
#pragma unroll
        for (int i = 0; i < 4; i++) {
            int idx = i * THREADS + tid;    // 0..1023
            int m = idx >> 4, kq4 = (idx & 15) * 4;
            hreg[i] = __ldcg((const float4*)&hp[(size_t)m * HH + k0 + kq4]);
        }

        int buf = 0;
        for (int c = 0; c < KSL / 64; c++) {     // 2 chunks
#pragma unroll
            for (int i = 0; i < 4; i++) {
                int idx = i * THREADS + tid;
                int m = idx >> 4, kq4 = (idx & 15) * 4;
                *(float4*)&hsb[buf * HBUF + m * HPAD + kq4] = hreg[i];
            }
            __syncthreads();
            if (c + 1 < KSL / 64) {
#pragma unroll
                for (int i = 0; i < 4; i++) {
                    int idx = i * THREADS + tid;
                    int m = idx >> 4, kq4 = (idx & 15) * 4;
                    hreg[i] = __ldcg((const float4*)&hp[(size_t)m * HH + k0 + (c + 1) * 64 + kq4]);
                }
            }
            const float* hb = hsb + buf * HBUF + (ty * 4) * HPAD;
            const float* wrow = ws + (c * 64) * NSL + tx * 4;
#pragma unroll 8
            for (int kk = 0; kk < 64; kk++) {
                const float* wr = wrow + kk * NSL;
                ulonglong2 b0 = *(const ulonglong2*)(wr);
                ulonglong2 b1 = *(const ulonglong2*)(wr + 64);
                ulonglong2 b2 = *(const ulonglong2*)(wr + 128);
                ulonglong2 b3 = *(const ulonglong2*)(wr + 192);
                float a0 = hb[kk];
                float a1 = hb[HPAD + kk];
                float a2 = hb[2 * HPAD + kk];
                float a3 = hb[3 * HPAD + kk];
                ull A0 = pack2(a0, a0), A1 = pack2(a1, a1);
                ull A2 = pack2(a2, a2), A3 = pack2(a3, a3);
#define FM(i, A)                                    \
                fma2(acc[i][0], A, b0.x); fma2(acc[i][1], A, b0.y); \
                fma2(acc[i][2], A, b1.x); fma2(acc[i][3], A, b1.y); \
                fma2(acc[i][4], A, b2.x); fma2(acc[i][5], A, b2.y); \
                fma2(acc[i][6], A, b3.x); fma2(acc[i][7], A, b3.y)
                FM(0, A0); FM(1, A1); FM(2, A2); FM(3, A3);
#undef FM
            }
            __syncthreads();
            buf ^= 1;
        }

        // write partial tile to g_part[kb]
        float* P = g_part + (size_t)kb * STEP_ELEMS;
#pragma unroll
        for (int i = 0; i < 4; i++) {
            const int m = ty * 4 + i;
#pragma unroll
            for (int q = 0; q < 4; q++) {
                float4 v;
                unpack2(acc[i][2 * q + 0], v.x, v.y);
                unpack2(acc[i][2 * q + 1], v.z, v.w);
                *(float4*)&P[(size_t)m * HH + nbase + q * 64 + tx * 4] = v;
            }
        }
        grid_barrier(epoch);   // barrier itself carries release/acquire

        // distributed epilogue: reduce 16 partials + x_proj, tanh, write out[t]
        {
            float4 s = __ldcg((const float4*)&g_part[eoff]);
#pragma unroll
            for (int k2 = 1; k2 < KBD; k2++) {
                float4 p = __ldcg((const float4*)&g_part[(size_t)k2 * STEP_ELEMS + eoff]);
                s.x += p.x; s.y += p.y; s.z += p.z; s.w += p.w;
            }
            const float4 xv = *(const float4*)&g_xproj[(size_t)t * STEP_ELEMS + eoff];
            float4 r;
            r.x = tanhf(s.x + xv.x);
            r.y = tanhf(s.y + xv.y);
            r.z = tanhf(s.z + xv.z);
            r.w = tanhf(s.w + xv.w);
            *(float4*)&out[(size_t)t * STEP_ELEMS + eoff] = r;
            if (t == TT - 1)
                *(float4*)&out[(size_t)TT * STEP_ELEMS + eoff] = r;   // final_state
        }
        grid_barrier(epoch);
    }
}

// -----------------------------------------------------------------------------
// x_proj = inputs[16384,1024] @ W_xh[1024,2048] + b_h
// -----------------------------------------------------------------------------
__global__ void __launch_bounds__(256) xproj_kernel(
    const float* __restrict__ A,
    const float* __restrict__ B,
    const float* __restrict__ bias)
{
    const int nb = blockIdx.x;
    const int mb = blockIdx.y;
    const int tid = threadIdx.x;
    const int tx = tid & 15;
    const int ty = tid >> 4;
    const int nbase = nb * 128;
    const int mbase = mb * 128;

    __shared__ __align__(16) float As[16][128];
    __shared__ __align__(16) float Bs[16][128];

    ull acc[8][4];
#pragma unroll
    for (int i = 0; i < 8; i++)
#pragma unroll
        for (int j = 0; j < 4; j++) acc[i][j] = 0ULL;

    float4 areg[2], breg[2];
#pragma unroll
    for (int it = 0; it < 2; it++) {
        int idx = tid + it * 256;
        int m = idx >> 2, kq = idx & 3;
        areg[it] = *(const float4*)(A + (size_t)(mbase + m) * DD + kq * 4);
        int kk = idx >> 5, c4 = idx & 31;
        breg[it] = *(const float4*)(B + (size_t)kk * HH + nbase + c4 * 4);
    }

    for (int ch = 0; ch < DD / 16; ch++) {
#pragma unroll
        for (int it = 0; it < 2; it++) {
            int idx = tid + it * 256;
            int m = idx >> 2, kq = idx & 3;
            As[kq * 4 + 0][m] = areg[it].x;
            As[kq * 4 + 1][m] = areg[it].y;
            As[kq * 4 + 2][m] = areg[it].z;
            As[kq * 4 + 3][m] = areg[it].w;
            int kk = idx >> 5, c4 = idx & 31;
            *(float4*)&Bs[kk][c4 * 4] = breg[it];
        }
        __syncthreads();
        if (ch + 1 < DD / 16) {
            const int k0 = (ch + 1) * 16;
#pragma unroll
            for (int it = 0; it < 2; it++) {
                int idx = tid + it * 256;
                int m = idx >> 2, kq = idx & 3;
                areg[it] = *(const float4*)(A + (size_t)(mbase + m) * DD + k0 + kq * 4);
                int kk = idx >> 5, c4 = idx & 31;
                breg[it] = *(const float4*)(B + (size_t)(k0 + kk) * HH + nbase + c4 * 4);
            }
        }
#pragma unroll
        for (int k = 0; k < 16; k++) {
            float4 a0 = *(const float4*)&As[k][ty * 4];
            float4 a1 = *(const float4*)&As[k][64 + ty * 4];
            ulonglong2 b0 = *(const ulonglong2*)&Bs[k][tx * 4];
            ulonglong2 b1 = *(const ulonglong2*)&Bs[k][64 + tx * 4];
            float a[8] = {a0.x, a0.y, a0.z, a0.w, a1.x, a1.y, a1.z, a1.w};
#pragma unroll
            for (int i = 0; i < 8; i++) {
                ull a2 = pack2(a[i], a[i]);
                fma2(acc[i][0], a2, b0.x);
                fma2(acc[i][1], a2, b0.y);
                fma2(acc[i][2], a2, b1.x);
                fma2(acc[i][3], a2, b1.y);
            }
        }
        __syncthreads();
    }

#pragma unroll
    for (int i = 0; i < 8; i++) {
        int r = (i < 4) ? (ty * 4 + i) : (64 + ty * 4 + i - 4);
        float o[8];
        unpack2(acc[i][0], o[0], o[1]);
        unpack2(acc[i][1], o[2], o[3]);
        unpack2(acc[i][2], o[4], o[5]);
        unpack2(acc[i][3], o[6], o[7]);
#pragma unroll
        for (int h = 0; h < 2; h++) {
            int col = nbase + h * 64 + tx * 4;
            float4 v;
            v.x = o[h * 4 + 0] + bias[col + 0];
            v.y = o[h * 4 + 1] + bias[col + 1];
            v.z = o[h * 4 + 2] + bias[col + 2];
            v.w = o[h * 4 + 3] + bias[col + 3];
            *(float4*)&g_xproj[(size_t)(mbase + r) * HH + col] = v;
        }
    }
}

extern "C" void kernel_launch(void* const* d_in, const int* in_sizes, int n_in,
                              void* d_out, int out_size)
{
    (void)in_sizes; (void)n_in; (void)out_size;
    const float* inputs = (const float*)d_in[0];   // [T,B,D]
    const float* state  = (const float*)d_in[1];   // [B,H]
    const float* W_xh   = (const float*)d_in[2];   // [D,H]
    const float* W_hh   = (const float*)d_in[3];   // [H,H]
    const float* b_h    = (const float*)d_in[4];   // [H]
    float* out = (float*)d_out;   // outputs [T,B,H] then final_state [B,H]

    const int smem_bytes = (KSL * NSL + 2 * 64 * 68) * sizeof(float);  // 165888
    cudaFuncSetAttribute(scan_kernel, cudaFuncAttributeMaxDynamicSharedMemorySize,
                         smem_bytes);

    // 1) x_proj for all steps
    xproj_kernel<<<dim3(HH / 128, (TT * BB) / 128), 256>>>(inputs, W_xh, b_h);

    // 2) persistent scan: all 256 steps in one launch
    scan_kernel<<<GRID, THREADS, smem_bytes>>>(state, W_hh, out);
}